// round 4
// baseline (speedup 1.0000x reference)
#include <cuda_runtime.h>
#include <cuda_bf16.h>
#include <math.h>
#include <stdint.h>

#define Bb 64
#define LL 196
#define TT 32
#define MAXT 31
#define ED 2048
#define AD 512
#define DD 512
#define VV 10000
#define XK 3072
#define FCN 10112
#define PGRID 148
#define GZ 8      /* gates k-split */
#define HZ 16     /* hU k-split   */

// d_out layout (float32): predictions, caps, dl, alphas, sort_idx
#define PRED_OFF  0
#define CAPS_OFF  (Bb*MAXT*VV)
#define DL_OFF    (CAPS_OFF + Bb*TT)
#define ALPHA_OFF (DL_OFF + Bb)
#define SIDX_OFF  (ALPHA_OFF + Bb*MAXT*LL)

// ------------------- static device scratch -------------------
__device__ int   g_sidx[Bb];
__device__ int   g_nb[MAXT];
__device__ float g_h[Bb*DD];
__device__ float g_c[Bb*DD];
__device__ float g_beta[Bb];
__device__ float g_energy[Bb*LL];
__device__ float g_WaEnc[(size_t)Bb*LL*AD];
__device__ float g_hUpart[HZ*Bb*AD];
__device__ float g_gatesPart[GZ*Bb*2048];
__device__ float g_initPart[16*Bb*DD];

__device__ uint2 g_encPk[(size_t)Bb*LL*(ED/2)];
__device__ uint2 g_WaT  [(size_t)AD*(ED/2)];
__device__ uint2 g_UaT  [(size_t)AD*(DD/2)];
__device__ uint2 g_WcatPk[(size_t)2048*(XK/2)];
__device__ uint2 g_fcT  [(size_t)FCN*(DD/2)];
__device__ uint2 g_ihT  [(size_t)DD*(ED/2)];
__device__ uint2 g_icT  [(size_t)DD*(ED/2)];
__device__ uint2 g_meanPk[Bb*(ED/2)];
__device__ uint2 g_xcatPk[Bb*(XK/2)];
__device__ uint2 g_hPk  [Bb*(DD/2)];

__device__ unsigned g_barCount = 0;
__device__ unsigned g_barGen = 0;

__device__ __forceinline__ float sigmoidf_(float x){ return 1.0f/(1.0f+expf(-x)); }
__device__ __forceinline__ float tanh_hw(float x){
    float r; asm("tanh.approx.f32 %0, %1;" : "=f"(r) : "f"(x)); return r;
}
__device__ __forceinline__ uint2 packsplit(float x0, float x1){
    __nv_bfloat16 h0 = __float2bfloat16_rn(x0);
    __nv_bfloat16 h1 = __float2bfloat16_rn(x1);
    __nv_bfloat16 l0 = __float2bfloat16_rn(x0 - __bfloat162float(h0));
    __nv_bfloat16 l1 = __float2bfloat16_rn(x1 - __bfloat162float(h1));
    uint2 u;
    u.x = (uint32_t)__bfloat16_as_ushort(h0) | ((uint32_t)__bfloat16_as_ushort(h1) << 16);
    u.y = (uint32_t)__bfloat16_as_ushort(l0) | ((uint32_t)__bfloat16_as_ushort(l1) << 16);
    return u;
}
__device__ __forceinline__ void mma16816(float* c,
    uint32_t a0, uint32_t a1, uint32_t a2, uint32_t a3, uint32_t b0, uint32_t b1)
{
    asm volatile(
        "mma.sync.aligned.m16n8k16.row.col.f32.bf16.bf16.f32 "
        "{%0,%1,%2,%3},{%4,%5,%6,%7},{%8,%9},{%0,%1,%2,%3};"
        : "+f"(c[0]), "+f"(c[1]), "+f"(c[2]), "+f"(c[3])
        : "r"(a0), "r"(a1), "r"(a2), "r"(a3), "r"(b0), "r"(b1));
}
__device__ __forceinline__ uint2 ldcg2(const uint2* p){
    uint2 r;
    asm volatile("ld.global.cg.v2.u32 {%0,%1}, [%2];" : "=r"(r.x), "=r"(r.y) : "l"(p));
    return r;
}
__device__ __forceinline__ float ldcgf(const float* p){
    float r; asm volatile("ld.global.cg.f32 %0, [%1];" : "=f"(r) : "l"(p)); return r;
}

// grid-wide barrier (all PGRID blocks co-resident)
__device__ __forceinline__ void gsync(){
    __syncthreads();
    if (threadIdx.x == 0) {
        __threadfence();
        unsigned gen = *(volatile unsigned*)&g_barGen;
        if (atomicInc(&g_barCount, PGRID - 1) == PGRID - 1) {
            *(volatile unsigned*)&g_barGen = gen + 1;
            __threadfence();
        } else {
            while (*(volatile unsigned*)&g_barGen == gen) __nanosleep(64);
            __threadfence();
        }
    }
    __syncthreads();
}

// ------------------- sort -------------------
__global__ void k_sort(const int* __restrict__ lengths, const int* __restrict__ captions,
                       float* __restrict__ out)
{
    __shared__ int slen[Bb];
    __shared__ int sdl[Bb];
    int i = threadIdx.x;
    slen[i] = lengths[i];
    __syncthreads();
    int li = slen[i];
    int rank = 0;
    #pragma unroll 8
    for (int j = 0; j < Bb; j++) {
        int lj = slen[j];
        if (lj > li || (lj == li && j < i)) rank++;
    }
    g_sidx[rank] = i;
    __syncthreads();
    int src = g_sidx[i];
    int dl  = slen[src] - 1;
    sdl[i] = dl;
    out[DL_OFF + i]   = (float)dl;
    out[SIDX_OFF + i] = (float)src;
    for (int t2 = 0; t2 < TT; t2++)
        out[CAPS_OFF + i*TT + t2] = (float)captions[src*TT + t2];
    __syncthreads();
    if (i < MAXT) {
        int c = 0;
        for (int j = 0; j < Bb; j++) if (sdl[j] > i) c++;
        g_nb[i] = c;
    }
}

// ------------------- setup conversions -------------------
__global__ void k_cvt_enc(const float* __restrict__ enc)
{
    int row = blockIdx.x;
    const float* r = enc + (size_t)row*ED;
    uint2* o = g_encPk + (size_t)row*(ED/2);
    #pragma unroll
    for (int i = 0; i < 4; i++) {
        int p = threadIdx.x + i*256;
        o[p] = packsplit(r[2*p], r[2*p+1]);
    }
}

__global__ void k_cvt_wT(const float* __restrict__ W, uint2* __restrict__ out,
                         int N, int NP, int Kp)
{
    int kp = blockIdx.x;
    int n = blockIdx.y*256 + threadIdx.x;
    if (n >= NP) return;
    float v0 = 0.f, v1 = 0.f;
    if (n < N) { v0 = W[(size_t)(2*kp)*N + n]; v1 = W[(size_t)(2*kp+1)*N + n]; }
    out[(size_t)n*Kp + kp] = packsplit(v0, v1);
}

__global__ void k_cvt_wcat(const float* __restrict__ W_ih, const float* __restrict__ W_hh)
{
    int n = blockIdx.x;
    uint2* o = g_WcatPk + (size_t)n*(XK/2);
    #pragma unroll
    for (int i = 0; i < 6; i++) {
        int kp = threadIdx.x + i*256;
        int k0 = 2*kp;
        float v0 = (k0   < 2560) ? W_ih[(size_t)n*2560 + k0]   : W_hh[(size_t)n*512 + (k0-2560)];
        float v1 = (k0+1 < 2560) ? W_ih[(size_t)n*2560 + k0+1] : W_hh[(size_t)n*512 + (k0+1-2560)];
        o[kp] = packsplit(v0, v1);
    }
}

__global__ void k_mean(const float* __restrict__ enc)
{
    int b = blockIdx.x;
    int p = blockIdx.y*256 + threadIdx.x;
    const float* base = enc + (size_t)g_sidx[b]*LL*ED;
    float s0 = 0.f, s1 = 0.f;
    #pragma unroll 4
    for (int l = 0; l < LL; l++) {
        s0 += base[(size_t)l*ED + 2*p];
        s1 += base[(size_t)l*ED + 2*p+1];
    }
    g_meanPk[b*(ED/2) + p] = packsplit(s0*(1.0f/196.0f), s1*(1.0f/196.0f));
}

// ------------------- bf16-split mma GEMM (setup: h0/c0, WaEnc) -------------------
template<bool GATHER>
__global__ void __launch_bounds__(256) wgemm(
    const uint2* __restrict__ A, const uint2* __restrict__ BT,
    float* __restrict__ C, int M, int Kp, int ldap, int ldbp, int ldc)
{
    int tid = threadIdx.x;
    int wid = tid >> 5, lane = tid & 31;
    int g = lane >> 2, t = lane & 3;
    int m0 = blockIdx.y*64 + (wid & 3)*16;
    int n0 = blockIdx.x*128 + (wid >> 2)*64;

    int kpPer = Kp / gridDim.z;
    int kp0 = blockIdx.z * kpPer, kp1 = kp0 + kpPer;
    C += (size_t)blockIdx.z * (size_t)M * (size_t)ldc;

    int rA = m0 + g, rB = m0 + g + 8;
    if (GATHER) {
        rA = g_sidx[rA / LL]*LL + (rA % LL);
        rB = g_sidx[rB / LL]*LL + (rB % LL);
    }
    const uint2* Arow0 = A + (size_t)rA*ldap + t;
    const uint2* Arow1 = A + (size_t)rB*ldap + t;

    float c[8][4];
    #pragma unroll
    for (int j = 0; j < 8; j++)
        #pragma unroll
        for (int q = 0; q < 4; q++) c[j][q] = 0.f;

    for (int kp = kp0; kp < kp1; kp += 8) {
        uint2 A0 = Arow0[kp], A2 = Arow0[kp+4];
        uint2 A1 = Arow1[kp], A3 = Arow1[kp+4];
        #pragma unroll
        for (int j = 0; j < 8; j++) {
            const uint2* Br = BT + (size_t)(n0 + j*8 + g)*ldbp + t;
            uint2 B0 = Br[kp], B1 = Br[kp+4];
            mma16816(c[j], A0.x, A1.x, A2.x, A3.x, B0.x, B1.x);
            mma16816(c[j], A0.x, A1.x, A2.x, A3.x, B0.y, B1.y);
            mma16816(c[j], A0.y, A1.y, A2.y, A3.y, B0.x, B1.x);
        }
    }
    #pragma unroll
    for (int j = 0; j < 8; j++) {
        int n = n0 + j*8 + 2*t;
        float* cr0 = C + (size_t)(m0 + g)*ldc + n;
        float* cr1 = C + (size_t)(m0 + g + 8)*ldc + n;
        cr0[0] = c[j][0]; cr0[1] = c[j][1];
        cr1[0] = c[j][2]; cr1[1] = c[j][3];
    }
}

// ------------------- h0/c0 reduce + tanh + pack -------------------
__global__ void k_init(const float* __restrict__ ih_b, const float* __restrict__ ic_b)
{
    int b = blockIdx.x;
    int j0 = threadIdx.x*2;
    float sh0 = 0.f, sh1 = 0.f, sc0 = 0.f, sc1 = 0.f;
    #pragma unroll
    for (int ks = 0; ks < 8; ks++) {
        const float* ph = g_initPart + ((size_t)ks*Bb + b)*DD;
        const float* pc = g_initPart + ((size_t)(8+ks)*Bb + b)*DD;
        sh0 += ph[j0]; sh1 += ph[j0+1];
        sc0 += pc[j0]; sc1 += pc[j0+1];
    }
    float h0v = tanhf(sh0 + ih_b[j0]), h1v = tanhf(sh1 + ih_b[j0+1]);
    float c0v = tanhf(sc0 + ic_b[j0]), c1v = tanhf(sc1 + ic_b[j0+1]);
    g_h[b*DD + j0] = h0v; g_h[b*DD + j0+1] = h1v;
    g_c[b*DD + j0] = c0v; g_c[b*DD + j0+1] = c1v;
    g_hPk[b*(DD/2) + threadIdx.x] = packsplit(h0v, h1v);
}

// ------------------- persistent kernel device helpers -------------------
// mma over M=64 rows of A; A loaded with ldcg (inter-block freshness)
__device__ __forceinline__ void mma_tile_cg(
    const uint2* __restrict__ A, const uint2* __restrict__ BT,
    int ldap, int ldbp, int n0base, int kp0, int kpN, float c[8][4])
{
    int tid = threadIdx.x;
    int wid = tid >> 5, lane = tid & 31;
    int g = lane >> 2, t = lane & 3;
    int m0 = (wid & 3)*16;
    int n0 = n0base + (wid >> 2)*64;
    const uint2* Arow0 = A + (size_t)(m0 + g)*ldap + t;
    const uint2* Arow1 = A + (size_t)(m0 + g + 8)*ldap + t;
    for (int kp = kp0; kp < kp0 + kpN; kp += 8) {
        uint2 A0 = ldcg2(Arow0 + kp), A2 = ldcg2(Arow0 + kp + 4);
        uint2 A1 = ldcg2(Arow1 + kp), A3 = ldcg2(Arow1 + kp + 4);
        #pragma unroll
        for (int j = 0; j < 8; j++) {
            const uint2* Br = BT + (size_t)(n0 + j*8 + g)*ldbp + t;
            uint2 B0 = Br[kp], B1 = Br[kp+4];
            mma16816(c[j], A0.x, A1.x, A2.x, A3.x, B0.x, B1.x);
            mma16816(c[j], A0.x, A1.x, A2.x, A3.x, B0.y, B1.y);
            mma16816(c[j], A0.y, A1.y, A2.y, A3.y, B0.x, B1.x);
        }
    }
}
__device__ __forceinline__ void store_tile(float* C, int ldc, int n0base, float c[8][4])
{
    int tid = threadIdx.x;
    int wid = tid >> 5, lane = tid & 31;
    int g = lane >> 2, t = lane & 3;
    int m0 = (wid & 3)*16;
    int n0 = n0base + (wid >> 2)*64;
    #pragma unroll
    for (int j = 0; j < 8; j++) {
        int n = n0 + j*8 + 2*t;
        float* cr0 = C + (size_t)(m0 + g)*ldc + n;
        float* cr1 = C + (size_t)(m0 + g + 8)*ldc + n;
        cr0[0] = c[j][0]; cr0[1] = c[j][1];
        cr1[0] = c[j][2]; cr1[1] = c[j][3];
    }
}

__device__ __forceinline__ void do_hU(int id)
{
    int nti = id & 3, z = id >> 2;
    float c[8][4];
    #pragma unroll
    for (int j = 0; j < 8; j++){ c[j][0]=0.f;c[j][1]=0.f;c[j][2]=0.f;c[j][3]=0.f; }
    mma_tile_cg(g_hPk, g_UaT, 256, 256, nti*128, z*(256/HZ), 256/HZ, c);
    store_tile(g_hUpart + (size_t)z*Bb*AD, 512, nti*128, c);
}

// ------------------- persistent kernel -------------------
__global__ void __launch_bounds__(256) k_persist(
    const float* __restrict__ enc, const int* __restrict__ caps,
    const float* __restrict__ embT, const float* __restrict__ fb_W,
    const float* __restrict__ fb_b, const float* __restrict__ w_att,
    const float* __restrict__ b_ih, const float* __restrict__ b_hh,
    const float* __restrict__ fc_b, float* __restrict__ out)
{
    int bid = blockIdx.x, tid = threadIdx.x;
    int warp = tid >> 5, lane = tid & 31;

    __shared__ float sHU[AD];
    __shared__ float sW2[AD];
    __shared__ float sAl[LL];
    __shared__ float sred[8];

    // ================= Phase P: prep for t=0 =================
    if (bid >= 79 && bid < 143) {
        do_hU(bid - 79);
    } else if (bid == 143) {
        for (int b = warp; b < Bb; b += 8) {
            float s = 0.f;
            #pragma unroll
            for (int i = 0; i < 16; i++)
                s += g_h[b*DD + lane + 32*i] * fb_W[lane + 32*i];
            #pragma unroll
            for (int o = 16; o > 0; o >>= 1) s += __shfl_xor_sync(0xffffffffu, s, o);
            if (lane == 0) g_beta[b] = sigmoidf_(s + fb_b[0]);
        }
    } else if (bid >= 144) {
        for (int i = 0; i < 16; i++) {
            int b = (bid - 144)*16 + i;
            int cap = caps[g_sidx[b]*TT + 0];
            g_xcatPk[(size_t)b*1536 + tid] =
                packsplit(embT[(size_t)cap*DD + 2*tid], embT[(size_t)cap*DD + 2*tid + 1]);
            g_xcatPk[(size_t)b*1536 + 1280 + tid] = g_hPk[b*256 + tid];
        }
    }
    gsync();

    for (int t = 0; t < MAXT; t++) {
        int nbt = g_nb[t];

        // ============ A1: attention energies ============
        if (bid < 128) {
            int b = bid >> 1, half = bid & 1;
            if (b < nbt) {
                for (int a = tid; a < AD; a += 256) {
                    float s = 0.f;
                    #pragma unroll
                    for (int z = 0; z < HZ; z++)
                        s += ldcgf(&g_hUpart[(size_t)z*Bb*AD + b*AD + a]);
                    sHU[a] = s;
                    sW2[a] = w_att[a];
                }
                __syncthreads();
                int lbase = half*98;
                for (int l = lbase + warp; l < lbase + 98; l += 8) {
                    const float* wa = g_WaEnc + ((size_t)b*LL + l)*AD;
                    float acc = 0.f;
                    #pragma unroll 4
                    for (int a = lane; a < AD; a += 32)
                        acc += tanh_hw(wa[a] + sHU[a]) * sW2[a];
                    #pragma unroll
                    for (int o = 16; o > 0; o >>= 1) acc += __shfl_xor_sync(0xffffffffu, acc, o);
                    if (lane == 0) g_energy[b*LL + l] = acc;
                }
            }
        }
        gsync();

        // ============ A2: softmax + context + pack ============
        if (bid < 128) {
            int b = bid >> 1, half = bid & 1;
            if (b < nbt) {
                float v = (tid < LL) ? ldcgf(&g_energy[b*LL + tid]) : -3.4e38f;
                float m = v;
                #pragma unroll
                for (int o = 16; o > 0; o >>= 1) m = fmaxf(m, __shfl_xor_sync(0xffffffffu, m, o));
                if (lane == 0) sred[warp] = m;
                __syncthreads();
                if (tid < 8) {
                    float mm = sred[tid];
                    #pragma unroll
                    for (int o = 4; o > 0; o >>= 1) mm = fmaxf(mm, __shfl_xor_sync(0xffu, mm, o));
                    if (tid == 0) sred[0] = mm;
                }
                __syncthreads();
                float mx = sred[0];
                __syncthreads();
                float p = (tid < LL) ? expf(v - mx) : 0.f;
                float s = p;
                #pragma unroll
                for (int o = 16; o > 0; o >>= 1) s += __shfl_xor_sync(0xffffffffu, s, o);
                if (lane == 0) sred[warp] = s;
                __syncthreads();
                if (tid < 8) {
                    float ss = sred[tid];
                    #pragma unroll
                    for (int o = 4; o > 0; o >>= 1) ss += __shfl_xor_sync(0xffu, ss, o);
                    if (tid == 0) sred[0] = ss;
                }
                __syncthreads();
                float alpha = p / sred[0];
                if (tid < LL) sAl[tid] = alpha;
                if (half == 0 && tid < LL)
                    out[ALPHA_OFF + ((size_t)b*MAXT + t)*LL + tid] = alpha;
                __syncthreads();

                float beta = ldcgf(&g_beta[b]);
                const float* pe = enc + (size_t)g_sidx[b]*LL*ED;
                #pragma unroll
                for (int k2 = 0; k2 < 2; k2++) {
                    int p2 = half*512 + k2*256 + tid;       // context pair index
                    const float* pp = pe + 2*p2;
                    float a0 = 0.f, a1 = 0.f;
                    #pragma unroll 4
                    for (int l = 0; l < LL; l++) {
                        float2 vv = *(const float2*)(pp + (size_t)l*ED);
                        float al = sAl[l];
                        a0 += al*vv.x; a1 += al*vv.y;
                    }
                    g_xcatPk[(size_t)b*1536 + 256 + p2] = packsplit(a0*beta, a1*beta);
                }
            }
        }
        gsync();

        // ============ B: gates mma (partials) ============
        if (bid < 128) {
            int nti = bid & 15, z = bid >> 4;
            float c[8][4];
            #pragma unroll
            for (int j = 0; j < 8; j++){ c[j][0]=0.f;c[j][1]=0.f;c[j][2]=0.f;c[j][3]=0.f; }
            mma_tile_cg(g_xcatPk, g_WcatPk, 1536, 1536, nti*128, z*(1536/GZ), 1536/GZ, c);
            store_tile(g_gatesPart + (size_t)z*Bb*2048, 2048, nti*128, c);
        }
        gsync();

        // ============ C: LSTM + beta + emb pack(t+1) ============
        if (bid < 64 && bid < nbt) {
            int b = bid;
            int j = 2*tid;
            float2 biI = *(const float2*)(b_ih + j),        bhI = *(const float2*)(b_hh + j);
            float2 biF = *(const float2*)(b_ih + 512 + j),  bhF = *(const float2*)(b_hh + 512 + j);
            float2 biG = *(const float2*)(b_ih + 1024 + j), bhG = *(const float2*)(b_hh + 1024 + j);
            float2 biO = *(const float2*)(b_ih + 1536 + j), bhO = *(const float2*)(b_hh + 1536 + j);
            float gi0 = biI.x + bhI.x, gi1 = biI.y + bhI.y;
            float gf0 = biF.x + bhF.x, gf1 = biF.y + bhF.y;
            float gg0 = biG.x + bhG.x, gg1 = biG.y + bhG.y;
            float go0 = biO.x + bhO.x, go1 = biO.y + bhO.y;
            #pragma unroll
            for (int z = 0; z < GZ; z++) {
                const float* gp = g_gatesPart + (size_t)z*Bb*2048 + b*2048;
                gi0 += ldcgf(gp + j);        gi1 += ldcgf(gp + j + 1);
                gf0 += ldcgf(gp + 512 + j);  gf1 += ldcgf(gp + 512 + j + 1);
                gg0 += ldcgf(gp + 1024 + j); gg1 += ldcgf(gp + 1024 + j + 1);
                go0 += ldcgf(gp + 1536 + j); go1 += ldcgf(gp + 1536 + j + 1);
            }
            float2 cv = *(float2*)&g_c[b*DD + j];
            float i0 = sigmoidf_(gi0), i1 = sigmoidf_(gi1);
            float f0 = sigmoidf_(gf0), f1 = sigmoidf_(gf1);
            float q0 = tanhf(gg0),     q1 = tanhf(gg1);
            float o0 = sigmoidf_(go0), o1 = sigmoidf_(go1);
            float c0 = f0*cv.x + i0*q0, c1 = f1*cv.y + i1*q1;
            float h0 = o0*tanhf(c0),    h1 = o1*tanhf(c1);
            *(float2*)&g_c[b*DD + j] = make_float2(c0, c1);
            uint2 hp = packsplit(h0, h1);
            g_hPk[b*256 + tid] = hp;
            g_xcatPk[(size_t)b*1536 + 1280 + tid] = hp;

            // beta
            float s = h0*fb_W[j] + h1*fb_W[j+1];
            #pragma unroll
            for (int o = 16; o > 0; o >>= 1) s += __shfl_xor_sync(0xffffffffu, s, o);
            if (lane == 0) sred[warp] = s;
            __syncthreads();
            if (tid == 0) {
                float tot = 0.f;
                #pragma unroll
                for (int w = 0; w < 8; w++) tot += sred[w];
                g_beta[b] = sigmoidf_(tot + fb_b[0]);
            }
            // emb pack for t+1 (t+1 <= 31 < TT)
            int cap = caps[g_sidx[b]*TT + t + 1];
            g_xcatPk[(size_t)b*1536 + tid] =
                packsplit(embT[(size_t)cap*DD + 2*tid], embT[(size_t)cap*DD + 2*tid + 1]);
        }
        gsync();

        // ============ D: fc (this t) + hU (next t) ============
        if (bid < 79) {
            float c[8][4];
            #pragma unroll
            for (int j = 0; j < 8; j++){ c[j][0]=0.f;c[j][1]=0.f;c[j][2]=0.f;c[j][3]=0.f; }
            mma_tile_cg(g_hPk, g_fcT, 256, 256, bid*128, 0, 256, c);
            // masked store with bias
            int wid = tid >> 5;
            int g2 = lane >> 2, t4 = lane & 3;
            int m0 = (wid & 3)*16;
            int n0 = bid*128 + (wid >> 2)*64;
            #pragma unroll
            for (int j = 0; j < 8; j++) {
                int n = n0 + j*8 + 2*t4;
                if (n + 1 < VV) {
                    float bb0 = fc_b[n], bb1 = fc_b[n+1];
                    int mA = m0 + g2, mB = m0 + g2 + 8;
                    if (mA < nbt) {
                        float* cr = out + PRED_OFF + ((size_t)mA*MAXT + t)*VV + n;
                        cr[0] = c[j][0] + bb0; cr[1] = c[j][1] + bb1;
                    }
                    if (mB < nbt) {
                        float* cr = out + PRED_OFF + ((size_t)mB*MAXT + t)*VV + n;
                        cr[0] = c[j][2] + bb0; cr[1] = c[j][3] + bb1;
                    }
                }
            }
        } else if (bid < 143) {
            do_hU(bid - 79);
        }
        gsync();
    }
}

// ------------------- host -------------------
extern "C" void kernel_launch(void* const* d_in, const int* in_sizes, int n_in,
                              void* d_out_v, int out_size)
{
    const float* enc   = (const float*)d_in[0];
    const int*   caps  = (const int*)  d_in[1];
    const int*   lens  = (const int*)  d_in[2];
    const float* embT  = (const float*)d_in[3];
    const float* W_a   = (const float*)d_in[4];
    const float* U_a   = (const float*)d_in[5];
    const float* w_att = (const float*)d_in[6];
    const float* fb_W  = (const float*)d_in[7];
    const float* fb_b  = (const float*)d_in[8];
    const float* W_ih  = (const float*)d_in[9];
    const float* W_hh  = (const float*)d_in[10];
    const float* b_ih  = (const float*)d_in[11];
    const float* b_hh  = (const float*)d_in[12];
    const float* fc_W  = (const float*)d_in[13];
    const float* fc_b  = (const float*)d_in[14];
    const float* ih_W  = (const float*)d_in[15];
    const float* ih_b  = (const float*)d_in[16];
    const float* ic_W  = (const float*)d_in[17];
    const float* ic_b  = (const float*)d_in[18];
    float* out = (float*)d_out_v;

    void *pEncPk, *pWaT, *pUaT, *pFcT, *pIhT, *pIcT, *pMeanPk, *pWaEnc, *pInit;
    cudaGetSymbolAddress(&pEncPk,  g_encPk);
    cudaGetSymbolAddress(&pWaT,    g_WaT);
    cudaGetSymbolAddress(&pUaT,    g_UaT);
    cudaGetSymbolAddress(&pFcT,    g_fcT);
    cudaGetSymbolAddress(&pIhT,    g_ihT);
    cudaGetSymbolAddress(&pIcT,    g_icT);
    cudaGetSymbolAddress(&pMeanPk, g_meanPk);
    cudaGetSymbolAddress(&pWaEnc,  g_WaEnc);
    cudaGetSymbolAddress(&pInit,   g_initPart);

    cudaMemsetAsync(out, 0, (size_t)out_size * sizeof(float), 0);

    k_sort<<<1, 64>>>(lens, caps, out);
    k_cvt_enc<<<Bb*LL, 256>>>(enc);
    k_cvt_wcat<<<2048, 256>>>(W_ih, W_hh);
    k_cvt_wT<<<dim3(ED/2, 2), 256>>>(W_a,  (uint2*)pWaT, AD, AD, ED/2);
    k_cvt_wT<<<dim3(DD/2, 2), 256>>>(U_a,  (uint2*)pUaT, AD, AD, DD/2);
    k_cvt_wT<<<dim3(DD/2, 40), 256>>>(fc_W, (uint2*)pFcT, VV, FCN, DD/2);
    k_cvt_wT<<<dim3(ED/2, 2), 256>>>(ih_W, (uint2*)pIhT, DD, DD, ED/2);
    k_cvt_wT<<<dim3(ED/2, 2), 256>>>(ic_W, (uint2*)pIcT, DD, DD, ED/2);
    k_mean<<<dim3(Bb, 4), 256>>>(enc);

    wgemm<false><<<dim3(4, 1, 8), 256>>>(
        (const uint2*)pMeanPk, (const uint2*)pIhT, (float*)pInit, 64, ED/2, ED/2, ED/2, 512);
    wgemm<false><<<dim3(4, 1, 8), 256>>>(
        (const uint2*)pMeanPk, (const uint2*)pIcT,
        (float*)pInit + (size_t)8*Bb*DD, 64, ED/2, ED/2, ED/2, 512);
    k_init<<<Bb, 256>>>(ih_b, ic_b);

    wgemm<true><<<dim3(4, 196, 1), 256>>>(
        (const uint2*)pEncPk, (const uint2*)pWaT, (float*)pWaEnc, 12544, ED/2, ED/2, ED/2, 512);

    k_persist<<<PGRID, 256>>>(enc, caps, embT, fb_W, fb_b, w_att, b_ih, b_hh, fc_b, out);
}

// round 5
// speedup vs baseline: 1.2940x; 1.2940x over previous
#include <cuda_runtime.h>
#include <cuda_bf16.h>
#include <math.h>
#include <stdint.h>

#define Bb 64
#define LL 196
#define TT 32
#define MAXT 31
#define ED 2048
#define AD 512
#define DD 512
#define VV 10000
#define XK 3072
#define HSPLIT 8
#define GSPLIT 12
#define FCLD 10112

// d_out layout (float32): predictions, caps, dl, alphas, sort_idx
#define PRED_OFF  0
#define CAPS_OFF  (Bb*MAXT*VV)
#define DL_OFF    (CAPS_OFF + Bb*TT)
#define ALPHA_OFF (DL_OFF + Bb)
#define SIDX_OFF  (ALPHA_OFF + Bb*MAXT*LL)

// ------------------- static device scratch -------------------
__device__ int   g_sidx[Bb];
__device__ int   g_nb[MAXT];
__device__ float g_mean[Bb*ED];
__device__ float g_h[Bb*DD];
__device__ float g_c[Bb*DD];
__device__ float g_WaEnc[(size_t)Bb*LL*AD];
__device__ float g_Wcat[(size_t)2048*XK];
__device__ float g_hUpart[HSPLIT*Bb*AD];
__device__ float g_beta[Bb];
__device__ float g_energy[Bb*LL];
__device__ float g_xcat[Bb*XK];                    // [emb | context | h]
__device__ float g_gatesPart[GSPLIT*Bb*2048];
__device__ float g_fcPart[2*Bb*FCLD];
__device__ float g_initPart[2*16*Bb*DD];

// packed bf16-split (setup only): uint2 {hi_pair, lo_pair}
__device__ uint2 g_encPk[(size_t)Bb*LL*(ED/2)];
__device__ uint2 g_WaT  [(size_t)AD*(ED/2)];

__device__ __forceinline__ float sigmoidf_(float x){ return 1.0f/(1.0f+expf(-x)); }
__device__ __forceinline__ uint2 packsplit(float x0, float x1){
    __nv_bfloat16 h0 = __float2bfloat16_rn(x0);
    __nv_bfloat16 h1 = __float2bfloat16_rn(x1);
    __nv_bfloat16 l0 = __float2bfloat16_rn(x0 - __bfloat162float(h0));
    __nv_bfloat16 l1 = __float2bfloat16_rn(x1 - __bfloat162float(h1));
    uint2 u;
    u.x = (uint32_t)__bfloat16_as_ushort(h0) | ((uint32_t)__bfloat16_as_ushort(h1) << 16);
    u.y = (uint32_t)__bfloat16_as_ushort(l0) | ((uint32_t)__bfloat16_as_ushort(l1) << 16);
    return u;
}
__device__ __forceinline__ void mma16816(float* c,
    uint32_t a0, uint32_t a1, uint32_t a2, uint32_t a3, uint32_t b0, uint32_t b1)
{
    asm volatile(
        "mma.sync.aligned.m16n8k16.row.col.f32.bf16.bf16.f32 "
        "{%0,%1,%2,%3},{%4,%5,%6,%7},{%8,%9},{%0,%1,%2,%3};"
        : "+f"(c[0]), "+f"(c[1]), "+f"(c[2]), "+f"(c[3])
        : "r"(a0), "r"(a1), "r"(a2), "r"(a3), "r"(b0), "r"(b1));
}

// ------------------- sort -------------------
__global__ void k_sort(const int* __restrict__ lengths, const int* __restrict__ captions,
                       float* __restrict__ out)
{
    __shared__ int slen[Bb];
    __shared__ int sdl[Bb];
    int i = threadIdx.x;
    slen[i] = lengths[i];
    __syncthreads();
    int li = slen[i];
    int rank = 0;
    #pragma unroll 8
    for (int j = 0; j < Bb; j++) {
        int lj = slen[j];
        if (lj > li || (lj == li && j < i)) rank++;
    }
    g_sidx[rank] = i;
    __syncthreads();
    int src = g_sidx[i];
    int dl  = slen[src] - 1;
    sdl[i] = dl;
    out[DL_OFF + i]   = (float)dl;
    out[SIDX_OFF + i] = (float)src;
    for (int t2 = 0; t2 < TT; t2++)
        out[CAPS_OFF + i*TT + t2] = (float)captions[src*TT + t2];
    __syncthreads();
    if (i < MAXT) {
        int c = 0;
        for (int j = 0; j < Bb; j++) if (sdl[j] > i) c++;
        g_nb[i] = c;
    }
}

// ------------------- setup: Wcat (fp32), enc pack, WaT pack, mean -------------------
__global__ void k_wcat(const float* __restrict__ W_ih, const float* __restrict__ W_hh)
{
    int j = blockIdx.x;
    for (int k = threadIdx.x; k < XK; k += 256)
        g_Wcat[(size_t)j*XK + k] = (k < 2560) ? W_ih[(size_t)j*2560 + k]
                                              : W_hh[(size_t)j*512 + (k - 2560)];
}

__global__ void k_cvt_enc(const float* __restrict__ enc)
{
    int row = blockIdx.x;
    const float* r = enc + (size_t)row*ED;
    uint2* o = g_encPk + (size_t)row*(ED/2);
    #pragma unroll
    for (int i = 0; i < 4; i++) {
        int p = threadIdx.x + i*256;
        o[p] = packsplit(r[2*p], r[2*p+1]);
    }
}

__global__ void k_cvt_waT(const float* __restrict__ W)
{
    int kp = blockIdx.x;                     // 0..1023
    int n  = blockIdx.y*256 + threadIdx.x;   // 0..511
    float v0 = W[(size_t)(2*kp)*AD + n];
    float v1 = W[(size_t)(2*kp+1)*AD + n];
    g_WaT[(size_t)n*(ED/2) + kp] = packsplit(v0, v1);
}

__global__ void k_mean(const float* __restrict__ enc)
{
    int b = blockIdx.x;
    int e = blockIdx.y*256 + threadIdx.x;
    const float* p = enc + (size_t)g_sidx[b]*LL*ED + e;
    float s = 0.f;
    #pragma unroll 4
    for (int l = 0; l < LL; l++) s += p[(size_t)l*ED];
    g_mean[b*ED + e] = s * (1.0f/196.0f);
}

// ------------------- setup mma GEMM for WaEnc (bf16-split, gathered A) -------------------
__global__ void __launch_bounds__(256) wgemm_waenc(
    const uint2* __restrict__ A, const uint2* __restrict__ BT, float* __restrict__ C)
{
    const int ldap = ED/2, ldbp = ED/2, ldc = AD;
    int tid = threadIdx.x;
    int wid = tid >> 5, lane = tid & 31;
    int g = lane >> 2, t = lane & 3;
    int m0 = blockIdx.y*64 + (wid & 3)*16;
    int n0 = blockIdx.x*128 + (wid >> 2)*64;

    int rA = m0 + g, rB = m0 + g + 8;
    rA = g_sidx[rA / LL]*LL + (rA % LL);
    rB = g_sidx[rB / LL]*LL + (rB % LL);
    const uint2* Arow0 = A + (size_t)rA*ldap + t;
    const uint2* Arow1 = A + (size_t)rB*ldap + t;

    float c[8][4];
    #pragma unroll
    for (int j = 0; j < 8; j++){ c[j][0]=0.f;c[j][1]=0.f;c[j][2]=0.f;c[j][3]=0.f; }

    for (int kp = 0; kp < ED/2; kp += 8) {
        uint2 A0 = Arow0[kp], A2 = Arow0[kp+4];
        uint2 A1 = Arow1[kp], A3 = Arow1[kp+4];
        #pragma unroll
        for (int j = 0; j < 8; j++) {
            const uint2* Br = BT + (size_t)(n0 + j*8 + g)*ldbp + t;
            uint2 B0 = Br[kp], B1 = Br[kp+4];
            mma16816(c[j], A0.x, A1.x, A2.x, A3.x, B0.x, B1.x);
            mma16816(c[j], A0.x, A1.x, A2.x, A3.x, B0.y, B1.y);
            mma16816(c[j], A0.y, A1.y, A2.y, A3.y, B0.x, B1.x);
        }
    }
    #pragma unroll
    for (int j = 0; j < 8; j++) {
        int n = n0 + j*8 + 2*t;
        float* cr0 = C + (size_t)(m0 + g)*ldc + n;
        float* cr1 = C + (size_t)(m0 + g + 8)*ldc + n;
        cr0[0] = c[j][0]; cr0[1] = c[j][1];
        cr1[0] = c[j][2]; cr1[1] = c[j][3];
    }
}

// ------------------- FP32 GEMM: 64x128 tile, 4x8 per thread, reg prefetch -------------------
template<bool TRANSB>
__global__ void __launch_bounds__(256) gemm2(
    const float* __restrict__ A, const float* __restrict__ Bm,
    float* __restrict__ C, int M, int N, int K, int lda, int ldc)
{
    const int BM=64, BN=128, BK=16;
    __shared__ float As[BK][BM];
    __shared__ float Bs[BK][BN];
    int bn = blockIdx.x*BN, bm = blockIdx.y*BM;
    int kPer = K / gridDim.z;
    int k0 = blockIdx.z * kPer;
    int nIter = kPer / BK;
    C += (size_t)blockIdx.z * (size_t)M * (size_t)ldc;

    int tid = threadIdx.x;
    int tx = tid & 15, ty = tid >> 4;
    int a_m = tid >> 2, a_k = (tid & 3) << 2;
    int b_k = tid >> 4;
    int b_n = (tid & 15) << 2;
    int r2  = tid >> 2;

    size_t arow = (size_t)(bm + a_m)*(size_t)lda;

    float4 aR, bR0, bR1;
    {
        int kk0 = k0;
        aR = *(const float4*)(A + arow + kk0 + a_k);
        if (TRANSB) {
            bR0 = *(const float4*)(Bm + (size_t)(bn + r2)      * (size_t)K + kk0 + a_k);
            bR1 = *(const float4*)(Bm + (size_t)(bn + 64 + r2) * (size_t)K + kk0 + a_k);
        } else {
            const float* br = Bm + (size_t)(kk0 + b_k)*(size_t)N;
            int n0 = bn + b_n, n1 = bn + 64 + b_n;
            if (n0 + 3 < N) bR0 = *(const float4*)(br + n0);
            else { bR0.x = n0<N?br[n0]:0.f; bR0.y = n0+1<N?br[n0+1]:0.f;
                   bR0.z = n0+2<N?br[n0+2]:0.f; bR0.w = 0.f; }
            if (n1 + 3 < N) bR1 = *(const float4*)(br + n1);
            else { bR1.x = n1<N?br[n1]:0.f; bR1.y = n1+1<N?br[n1+1]:0.f;
                   bR1.z = n1+2<N?br[n1+2]:0.f; bR1.w = 0.f; }
        }
    }

    float acc[4][8];
    #pragma unroll
    for (int i = 0; i < 4; i++)
        #pragma unroll
        for (int j = 0; j < 8; j++) acc[i][j] = 0.f;

    for (int it = 0; it < nIter; it++) {
        As[a_k+0][a_m] = aR.x; As[a_k+1][a_m] = aR.y;
        As[a_k+2][a_m] = aR.z; As[a_k+3][a_m] = aR.w;
        if (TRANSB) {
            Bs[a_k+0][r2] = bR0.x; Bs[a_k+1][r2] = bR0.y;
            Bs[a_k+2][r2] = bR0.z; Bs[a_k+3][r2] = bR0.w;
            Bs[a_k+0][64+r2] = bR1.x; Bs[a_k+1][64+r2] = bR1.y;
            Bs[a_k+2][64+r2] = bR1.z; Bs[a_k+3][64+r2] = bR1.w;
        } else {
            *(float4*)&Bs[b_k][b_n]      = bR0;
            *(float4*)&Bs[b_k][64 + b_n] = bR1;
        }
        __syncthreads();

        if (it + 1 < nIter) {
            int kk0 = k0 + (it+1)*BK;
            aR = *(const float4*)(A + arow + kk0 + a_k);
            if (TRANSB) {
                bR0 = *(const float4*)(Bm + (size_t)(bn + r2)      * (size_t)K + kk0 + a_k);
                bR1 = *(const float4*)(Bm + (size_t)(bn + 64 + r2) * (size_t)K + kk0 + a_k);
            } else {
                const float* br = Bm + (size_t)(kk0 + b_k)*(size_t)N;
                int n0 = bn + b_n, n1 = bn + 64 + b_n;
                if (n0 + 3 < N) bR0 = *(const float4*)(br + n0);
                else { bR0.x = n0<N?br[n0]:0.f; bR0.y = n0+1<N?br[n0+1]:0.f;
                       bR0.z = n0+2<N?br[n0+2]:0.f; bR0.w = 0.f; }
                if (n1 + 3 < N) bR1 = *(const float4*)(br + n1);
                else { bR1.x = n1<N?br[n1]:0.f; bR1.y = n1+1<N?br[n1+1]:0.f;
                       bR1.z = n1+2<N?br[n1+2]:0.f; bR1.w = 0.f; }
            }
        }

        #pragma unroll
        for (int kk = 0; kk < BK; kk++) {
            float4 av = *(const float4*)&As[kk][ty*4];
            float4 b0 = *(const float4*)&Bs[kk][tx*4];
            float4 b1 = *(const float4*)&Bs[kk][64 + tx*4];
            float a[4] = {av.x, av.y, av.z, av.w};
            #pragma unroll
            for (int i = 0; i < 4; i++) {
                acc[i][0] += a[i]*b0.x; acc[i][1] += a[i]*b0.y;
                acc[i][2] += a[i]*b0.z; acc[i][3] += a[i]*b0.w;
                acc[i][4] += a[i]*b1.x; acc[i][5] += a[i]*b1.y;
                acc[i][6] += a[i]*b1.z; acc[i][7] += a[i]*b1.w;
            }
        }
        __syncthreads();
    }

    int n0 = bn + tx*4, n1 = bn + 64 + tx*4;
    #pragma unroll
    for (int i = 0; i < 4; i++) {
        int m = bm + ty*4 + i;
        float* cr = C + (size_t)m*(size_t)ldc;
        if (n0 + 3 < N) { *(float4*)(cr + n0) = *(float4*)&acc[i][0]; }
        else { for (int j = 0; j < 4; j++) if (n0 + j < N) cr[n0+j] = acc[i][j]; }
        if (n1 + 3 < N) { *(float4*)(cr + n1) = *(float4*)&acc[i][4]; }
        else { for (int j = 0; j < 4; j++) if (n1 + j < N) cr[n1+j] = acc[i][4+j]; }
    }
}

// ------------------- h0/c0 reduce + tanh -------------------
__global__ void k_init(const float* __restrict__ ih_b, const float* __restrict__ ic_b)
{
    int b = blockIdx.x;
    for (int j = threadIdx.x; j < DD; j += 256) {
        float sh = 0.f, sc = 0.f;
        #pragma unroll
        for (int ks = 0; ks < 16; ks++) {
            sh += g_initPart[((size_t)ks*Bb + b)*DD + j];
            sc += g_initPart[((size_t)(16+ks)*Bb + b)*DD + j];
        }
        g_h[b*DD + j] = tanhf(sh + ih_b[j]);
        g_c[b*DD + j] = tanhf(sc + ic_b[j]);
    }
}

// ------------------- energies + prestep (emb/h copy, beta) -------------------
__global__ void k_energy(const int* __restrict__ captions, const float* __restrict__ embT,
                         const float* __restrict__ fb_W, const float* __restrict__ fb_b,
                         const float* __restrict__ w_att, int t)
{
    int b = blockIdx.x;
    if (b >= g_nb[t]) return;
    int yc = blockIdx.y;
    int tid = threadIdx.x;
    __shared__ float sHU[AD];
    __shared__ float sW[AD];
    __shared__ float sB[8];

    for (int a = tid; a < AD; a += 256) {
        float s = 0.f;
        #pragma unroll
        for (int ks = 0; ks < HSPLIT; ks++)
            s += g_hUpart[((size_t)ks*Bb + b)*AD + a];
        sHU[a] = s;
        sW[a]  = w_att[a];
    }

    if (yc == 0) {
        int cap = captions[g_sidx[b]*TT + t];
        if (tid < 128)
            ((float4*)(g_xcat + (size_t)b*XK))[tid] =
                ((const float4*)(embT + (size_t)cap*DD))[tid];
        else
            ((float4*)(g_xcat + (size_t)b*XK + 2560))[tid-128] =
                ((const float4*)(g_h + (size_t)b*DD))[tid-128];
        float s = g_h[b*DD + tid]       * fb_W[tid]
                + g_h[b*DD + 256 + tid] * fb_W[256 + tid];
        #pragma unroll
        for (int o = 16; o > 0; o >>= 1) s += __shfl_xor_sync(0xffffffffu, s, o);
        if ((tid & 31) == 0) sB[tid >> 5] = s;
    }
    __syncthreads();
    if (yc == 0 && tid == 0) {
        float tot = 0.f;
        #pragma unroll
        for (int w = 0; w < 8; w++) tot += sB[w];
        g_beta[b] = 1.0f / (1.0f + expf(-(tot + fb_b[0])));
    }

    int warp = tid >> 5, lane = tid & 31;
    int lend = min(yc*49 + 49, LL);
    for (int li = yc*49 + warp; li < lend; li += 8) {
        const float* wa = g_WaEnc + ((size_t)b*LL + li)*AD;
        float acc = 0.f;
        for (int a = lane; a < AD; a += 32)
            acc += tanhf(wa[a] + sHU[a]) * sW[a];
        #pragma unroll
        for (int o = 16; o > 0; o >>= 1) acc += __shfl_xor_sync(0xffffffffu, acc, o);
        if (lane == 0) g_energy[b*LL + li] = acc;
    }
}

// ------------------- softmax + context + alpha out -------------------
__global__ void k_context(const float* __restrict__ enc, float* __restrict__ out, int t)
{
    int b = blockIdx.x;
    if (b >= g_nb[t]) return;
    int ec = blockIdx.y;
    int tid = threadIdx.x;
    __shared__ float sAl[LL];
    __shared__ float sred[8];

    float v = (tid < LL) ? g_energy[b*LL + tid] : -3.4e38f;
    float m = v;
    #pragma unroll
    for (int o = 16; o > 0; o >>= 1) m = fmaxf(m, __shfl_xor_sync(0xffffffffu, m, o));
    if ((tid & 31) == 0) sred[tid >> 5] = m;
    __syncthreads();
    if (tid < 8) {
        float mm = sred[tid];
        #pragma unroll
        for (int o = 4; o > 0; o >>= 1) mm = fmaxf(mm, __shfl_xor_sync(0xffu, mm, o));
        if (tid == 0) sred[0] = mm;
    }
    __syncthreads();
    float mx = sred[0];
    __syncthreads();

    float p = (tid < LL) ? expf(v - mx) : 0.f;
    float s = p;
    #pragma unroll
    for (int o = 16; o > 0; o >>= 1) s += __shfl_xor_sync(0xffffffffu, s, o);
    if ((tid & 31) == 0) sred[tid >> 5] = s;
    __syncthreads();
    if (tid < 8) {
        float ss = sred[tid];
        #pragma unroll
        for (int o = 4; o > 0; o >>= 1) ss += __shfl_xor_sync(0xffu, ss, o);
        if (tid == 0) sred[0] = ss;
    }
    __syncthreads();
    float alpha = p / sred[0];
    if (tid < LL) sAl[tid] = alpha;
    if (ec == 0 && tid < LL)
        out[ALPHA_OFF + ((size_t)b*MAXT + t)*LL + tid] = alpha;
    __syncthreads();

    int e = ec*256 + tid;
    const float* pe = enc + (size_t)g_sidx[b]*LL*ED + e;
    float acc = 0.f;
    #pragma unroll 4
    for (int l = 0; l < LL; l++) acc += sAl[l] * pe[(size_t)l*ED];
    g_xcat[(size_t)b*XK + 512 + e] = acc * g_beta[b];
}

// ------------------- gate reduce + LSTM pointwise -------------------
__global__ void k_lstm(const float* __restrict__ b_ih, const float* __restrict__ b_hh, int t)
{
    int b = blockIdx.x;
    if (b >= g_nb[t]) return;
    int tid = threadIdx.x;
    #pragma unroll
    for (int jj = 0; jj < 2; jj++) {
        int j = tid + jj*256;
        float gi = b_ih[j]        + b_hh[j];
        float gf = b_ih[512 + j]  + b_hh[512 + j];
        float gg = b_ih[1024 + j] + b_hh[1024 + j];
        float go = b_ih[1536 + j] + b_hh[1536 + j];
        #pragma unroll
        for (int ks = 0; ks < GSPLIT; ks++) {
            const float* gp = g_gatesPart + ((size_t)ks*Bb + b)*2048;
            gi += gp[j]; gf += gp[512 + j]; gg += gp[1024 + j]; go += gp[1536 + j];
        }
        float i_ = sigmoidf_(gi);
        float f_ = sigmoidf_(gf);
        float g2 = tanhf(gg);
        float o_ = sigmoidf_(go);
        float c = f_ * g_c[b*DD + j] + i_ * g2;
        float h = o_ * tanhf(c);
        g_c[b*DD + j] = c;
        g_h[b*DD + j] = h;
    }
}

// ------------------- fc partial reduce + bias + masked store -------------------
__global__ void k_fcred(const float* __restrict__ fc_b, float* __restrict__ out, int t)
{
    int b = blockIdx.y;
    if (b >= g_nb[t]) return;
    int n = blockIdx.x*256 + threadIdx.x;
    if (n >= VV) return;
    float v = g_fcPart[(size_t)b*FCLD + n]
            + g_fcPart[(size_t)(Bb + b)*FCLD + n]
            + fc_b[n];
    out[PRED_OFF + (size_t)b*MAXT*VV + (size_t)t*VV + n] = v;
}

// ------------------- host -------------------
extern "C" void kernel_launch(void* const* d_in, const int* in_sizes, int n_in,
                              void* d_out_v, int out_size)
{
    const float* enc   = (const float*)d_in[0];
    const int*   caps  = (const int*)  d_in[1];
    const int*   lens  = (const int*)  d_in[2];
    const float* embT  = (const float*)d_in[3];
    const float* W_a   = (const float*)d_in[4];
    const float* U_a   = (const float*)d_in[5];
    const float* w_att = (const float*)d_in[6];
    const float* fb_W  = (const float*)d_in[7];
    const float* fb_b  = (const float*)d_in[8];
    const float* W_ih  = (const float*)d_in[9];
    const float* W_hh  = (const float*)d_in[10];
    const float* b_ih  = (const float*)d_in[11];
    const float* b_hh  = (const float*)d_in[12];
    const float* fc_W  = (const float*)d_in[13];
    const float* fc_b  = (const float*)d_in[14];
    const float* ih_W  = (const float*)d_in[15];
    const float* ih_b  = (const float*)d_in[16];
    const float* ic_W  = (const float*)d_in[17];
    const float* ic_b  = (const float*)d_in[18];
    float* out = (float*)d_out_v;

    void *pMean, *pH, *pWaEnc, *pWcat, *pHU, *pXcat, *pGates, *pFc, *pInit, *pEncPk, *pWaT;
    cudaGetSymbolAddress(&pMean,  g_mean);
    cudaGetSymbolAddress(&pH,     g_h);
    cudaGetSymbolAddress(&pWaEnc, g_WaEnc);
    cudaGetSymbolAddress(&pWcat,  g_Wcat);
    cudaGetSymbolAddress(&pHU,    g_hUpart);
    cudaGetSymbolAddress(&pXcat,  g_xcat);
    cudaGetSymbolAddress(&pGates, g_gatesPart);
    cudaGetSymbolAddress(&pFc,    g_fcPart);
    cudaGetSymbolAddress(&pInit,  g_initPart);
    cudaGetSymbolAddress(&pEncPk, g_encPk);
    cudaGetSymbolAddress(&pWaT,   g_WaT);

    cudaMemsetAsync(out, 0, (size_t)out_size * sizeof(float), 0);

    k_sort<<<1, 64>>>(lens, caps, out);
    k_wcat<<<2048, 256>>>(W_ih, W_hh);
    k_cvt_enc<<<Bb*LL, 256>>>(enc);
    k_cvt_waT<<<dim3(ED/2, 2), 256>>>(W_a);
    k_mean<<<dim3(64,8), 256>>>(enc);

    // h0/c0 partials: 64x512, K=2048, z=16 (fp32)
    gemm2<false><<<dim3(4,1,16), 256>>>(
        (const float*)pMean, ih_W, (float*)pInit, 64, 512, 2048, 2048, 512);
    gemm2<false><<<dim3(4,1,16), 256>>>(
        (const float*)pMean, ic_W, (float*)pInit + (size_t)16*64*512, 64, 512, 2048, 2048, 512);
    k_init<<<64, 256>>>(ih_b, ic_b);

    // WaEnc = enc[sidx] @ W_a via tensor cores: 12544 x 512, K=2048
    wgemm_waenc<<<dim3(4, 196), 256>>>(
        (const uint2*)pEncPk, (const uint2*)pWaT, (float*)pWaEnc);

    for (int t = 0; t < MAXT; t++) {
        // hU partials: 64x512, K=512, z=8 (fp32)
        gemm2<false><<<dim3(4,1,HSPLIT), 256>>>(
            (const float*)pH, U_a, (float*)pHU, 64, 512, 512, 512, 512);

        k_energy<<<dim3(64,4), 256>>>(caps, embT, fb_W, fb_b, w_att, t);
        k_context<<<dim3(64,8), 256>>>(enc, out, t);

        // gates partials: 64x2048, K=3072 (xcat @ Wcat^T), z=12 (fp32)
        gemm2<true><<<dim3(16,1,GSPLIT), 256>>>(
            (const float*)pXcat, (const float*)pWcat, (float*)pGates,
            64, 2048, XK, XK, 2048);

        k_lstm<<<64, 256>>>(b_ih, b_hh, t);

        // fc partials: 64x10000, K=512, z=2 (fp32)
        gemm2<false><<<dim3(79,1,2), 256>>>(
            (const float*)pH, fc_W, (float*)pFc, 64, VV, 512, 512, FCLD);
        k_fcred<<<dim3(40,64), 256>>>(fc_b, out, t);
    }
}